// round 2
// baseline (speedup 1.0000x reference)
#include <cuda_runtime.h>
#include <math.h>

#define NN   4096
#define DIN  3000
#define DHID 512
#define DOUT 64

// ---------------- scratch (device globals; no runtime allocation) ----------------
__device__ float g_att [(size_t)NN * NN];     // 64 MB attention matrix (reused 10x)
__device__ float g_bufA[(size_t)NN * DHID];   // layer-1 Wh (shared across views)
__device__ float g_bufB[(size_t)NN * DHID];
__device__ float g_bufC[(size_t)NN * DHID];
__device__ float g_big [(size_t)NN * DIN];    // decoder layer-2 Wh (4096x3000)
__device__ float g_embF[NN * DOUT];
__device__ float g_embS[NN * DOUT];
__device__ float g_s   [4 * NN];              // s1/s2 score vectors (2 pairs)
__device__ float g_vu  [2 * NN];
__device__ float g_part[(size_t)8 * NN * DOUT]; // split-K partials (deterministic)

// ---------------- SGEMM: C[M,N] = A[M,K] @ B[K,N], optional ELU epilogue ----------
// BM=BN=128, BK=8, 256 threads, 8x8 per thread. Requires M%128==0, K%8==0
// (holds for all shapes here: M=4096, K in {64,512,3000,4096}); N arbitrary.
// gridDim.z = split-K factor; when >1, C is a partials buffer of z slices
// (epilogue then applied by reduce_epi).
__global__ void sgemm_k(const float* __restrict__ A, const float* __restrict__ B,
                        float* __restrict__ C, int M, int N, int K, int epi)
{
    __shared__ float As[8][128];
    __shared__ float Bs[8][128];
    const int tid = threadIdx.x;
    const int tx  = tid & 15;
    const int ty  = tid >> 4;
    const int bm  = blockIdx.y;
    const int bn  = blockIdx.x;
    const int kChunk = K / gridDim.z;
    const int kBeg   = blockIdx.z * kChunk;
    C += (size_t)blockIdx.z * ((size_t)M * N);

    const int arow = tid >> 1;          // 0..127
    const int acol = (tid & 1) * 4;     // 0 or 4
    const float* Aptr = A + (size_t)(bm * 128 + arow) * K + kBeg + acol;

    const int brow  = tid >> 5;         // 0..7
    const int bcol  = (tid & 31) * 4;   // 0..124
    const int bgcol = bn * 128 + bcol;
    const float* Bptr = B + (size_t)(kBeg + brow) * N + bgcol;

    float acc[8][8];
#pragma unroll
    for (int i = 0; i < 8; i++)
#pragma unroll
        for (int j = 0; j < 8; j++) acc[i][j] = 0.f;

    for (int k0 = 0; k0 < kChunk; k0 += 8) {
        float4 av = *(const float4*)Aptr;
        As[acol + 0][arow] = av.x;
        As[acol + 1][arow] = av.y;
        As[acol + 2][arow] = av.z;
        As[acol + 3][arow] = av.w;
        if (bgcol + 3 < N) {
            *(float4*)&Bs[brow][bcol] = *(const float4*)Bptr;
        } else {
            Bs[brow][bcol + 0] = (bgcol + 0 < N) ? Bptr[0] : 0.f;
            Bs[brow][bcol + 1] = (bgcol + 1 < N) ? Bptr[1] : 0.f;
            Bs[brow][bcol + 2] = (bgcol + 2 < N) ? Bptr[2] : 0.f;
            Bs[brow][bcol + 3] = (bgcol + 3 < N) ? Bptr[3] : 0.f;
        }
        __syncthreads();
#pragma unroll
        for (int k = 0; k < 8; k++) {
            float4 a0 = *(const float4*)&As[k][ty * 4];
            float4 a1 = *(const float4*)&As[k][ty * 4 + 64];
            float4 b0 = *(const float4*)&Bs[k][tx * 4];
            float4 b1 = *(const float4*)&Bs[k][tx * 4 + 64];
            float ar[8] = {a0.x, a0.y, a0.z, a0.w, a1.x, a1.y, a1.z, a1.w};
            float br[8] = {b0.x, b0.y, b0.z, b0.w, b1.x, b1.y, b1.z, b1.w};
#pragma unroll
            for (int i = 0; i < 8; i++)
#pragma unroll
                for (int j = 0; j < 8; j++)
                    acc[i][j] = fmaf(ar[i], br[j], acc[i][j]);
        }
        __syncthreads();
        Aptr += 8;
        Bptr += (size_t)8 * N;
    }

#pragma unroll
    for (int i = 0; i < 8; i++) {
        int row = bm * 128 + ((i < 4) ? (ty * 4 + i) : (64 + ty * 4 + i - 4));
#pragma unroll
        for (int j = 0; j < 8; j++) {
            int col = bn * 128 + ((j < 4) ? (tx * 4 + j) : (64 + tx * 4 + j - 4));
            if (col < N) {
                float v = acc[i][j];
                if (epi) v = (v > 0.f) ? v : expm1f(v);   // ELU
                C[(size_t)row * N + col] = v;
            }
        }
    }
}

// sum split-K partials (fixed order => deterministic), optional ELU
__global__ void reduce_epi(const float* __restrict__ part, float* __restrict__ out,
                           int MNtot, int S, int epi)
{
    int t = blockIdx.x * blockDim.x + threadIdx.x;
    if (t >= MNtot) return;
    float v = 0.f;
    for (int s = 0; s < S; s++) v += part[(size_t)s * MNtot + t];
    if (epi) v = (v > 0.f) ? v : expm1f(v);
    out[t] = v;
}

// ---------------- GAT attention-score vectors: s1 = Wh@a[:f], s2 = Wh@a[f:] -------
__global__ void scores_kernel(const float* __restrict__ WH, int f,
                              const float* __restrict__ a,
                              float* __restrict__ s1, float* __restrict__ s2)
{
    __shared__ float r1[256], r2[256];
    const int i = blockIdx.x, tid = threadIdx.x;
    const float* row = WH + (size_t)i * f;
    float l1 = 0.f, l2 = 0.f;
    for (int c = tid; c < f; c += 256) {
        float w = row[c];
        l1 += w * a[c];
        l2 += w * a[c + f];
    }
    r1[tid] = l1; r2[tid] = l2;
    __syncthreads();
    for (int s = 128; s > 0; s >>= 1) {
        if (tid < s) { r1[tid] += r1[tid + s]; r2[tid] += r2[tid + s]; }
        __syncthreads();
    }
    if (tid == 0) { s1[i] = r1[0]; s2[i] = r2[0]; }
}

// ---------------- att[i,:] = softmax_j( adj[i,j]>0 ? lrelu(s1[i]+s2[j]) : -9e15 ) --
__global__ void att_kernel(const float* __restrict__ s1, const float* __restrict__ s2,
                           const int* __restrict__ adj, float* __restrict__ att)
{
    __shared__ float esh[NN];     // 16 KB: staged e-row (then exp(e-m))
    __shared__ float red[256];
    const int i = blockIdx.x;
    const int tid = threadIdx.x;
    const float s1i = s1[i];
    const int* arow = adj + (size_t)i * NN;

    float lmax = -3.4e38f;
    for (int j = tid; j < NN; j += 256) {
        float x = s1i + s2[j];
        x = (x > 0.f) ? x : 0.2f * x;            // leaky_relu(0.2)
        float e = (arow[j] > 0) ? x : -9e15f;    // MASK_FILL
        esh[j] = e;
        lmax = fmaxf(lmax, e);
    }
    red[tid] = lmax; __syncthreads();
    for (int s = 128; s > 0; s >>= 1) {
        if (tid < s) red[tid] = fmaxf(red[tid], red[tid + s]);
        __syncthreads();
    }
    const float m = red[0];
    __syncthreads();

    float lsum = 0.f;
    for (int j = tid; j < NN; j += 256) {
        float p = expf(esh[j] - m);
        esh[j] = p;
        lsum += p;
    }
    red[tid] = lsum; __syncthreads();
    for (int s = 128; s > 0; s >>= 1) {
        if (tid < s) red[tid] += red[tid + s];
        __syncthreads();
    }
    const float inv = 1.f / red[0];

    float* orow = att + (size_t)i * NN;
    for (int j = tid; j < NN; j += 256) orow[j] = esh[j] * inv;
}

// ---------------- fusion: vu[i] = tanh(emb[i]@w_omega) @ u_omega ------------------
__global__ void vu_kernel(const float* __restrict__ emb, const float* __restrict__ w,
                          const float* __restrict__ u, float* __restrict__ vu)
{
    __shared__ float er[64];
    __shared__ float red[64];
    const int i = blockIdx.x, k = threadIdx.x;   // 64 threads
    er[k] = emb[(size_t)i * 64 + k];
    __syncthreads();
    float acc = 0.f;
#pragma unroll
    for (int d = 0; d < 64; d++) acc += er[d] * w[d * 64 + k];
    red[k] = tanhf(acc) * u[k];
    __syncthreads();
    for (int s = 32; s > 0; s >>= 1) {
        if (k < s) red[k] += red[k + s];
        __syncthreads();
    }
    if (k == 0) vu[i] = red[0];
}

// fused = a0*e1 + a1*e2, alpha = softmax(vu+1e-6) over the 2 views
__global__ void fuse_kernel(const float* __restrict__ e1, const float* __restrict__ e2,
                            const float* __restrict__ vu1, const float* __restrict__ vu2,
                            float* __restrict__ fused, float* __restrict__ alpha)
{
    const int i = blockIdx.x, d = threadIdx.x;   // 64 threads
    float x0 = vu1[i] + 1e-6f, x1 = vu2[i] + 1e-6f;
    float m = fmaxf(x0, x1);
    float p0 = expf(x0 - m), p1 = expf(x1 - m);
    float inv = 1.f / (p0 + p1);
    float a0 = p0 * inv, a1 = p1 * inv;
    fused[(size_t)i * 64 + d] = a0 * e1[(size_t)i * 64 + d] + a1 * e2[(size_t)i * 64 + d];
    if (alpha != 0 && d < 2) alpha[(size_t)i * 2 + d] = (d == 0) ? a0 : a1;
}

// ---------------- host orchestration ----------------------------------------------
static inline void run_gemm(const float* A, const float* B, float* C,
                            int M, int N, int K, int epi, int splits)
{
    dim3 grid((N + 127) / 128, M / 128, splits);
    sgemm_k<<<grid, 256>>>(A, B, C, M, N, K, epi);
}

// one GAT encoder stack (layer1 att+agg with shared WH1, then layer2) for one view
static void encode_view(const float* WH1, const float* sA1, const float* sB1,
                        const int* adj, const float* W_enc2, const float* a_enc2,
                        float* emb_out,
                        float* att, float* bufB, float* bufC, float* part,
                        float* sA2, float* sB2)
{
    att_kernel<<<NN, 256>>>(sA1, sB1, adj, att);
    run_gemm(att, WH1, bufB, NN, DHID, NN, 1, 1);                 // h1 = elu(att@WH1)
    run_gemm(bufB, W_enc2, part, NN, DOUT, DHID, 0, 4);           // WH2 (split-K=4)
    reduce_epi<<<(NN * DOUT + 255) / 256, 256>>>(part, bufC, NN * DOUT, 4, 0);
    scores_kernel<<<NN, 256>>>(bufC, DOUT, a_enc2, sA2, sB2);
    att_kernel<<<NN, 256>>>(sA2, sB2, adj, att);
    run_gemm(att, bufC, part, NN, DOUT, NN, 0, 8);                // att@WH2 (split-K=8)
    reduce_epi<<<(NN * DOUT + 255) / 256, 256>>>(part, emb_out, NN * DOUT, 8, 1); // elu
}

extern "C" void kernel_launch(void* const* d_in, const int* in_sizes, int n_in,
                              void* d_out, int out_size)
{
    const float* X       = (const float*)d_in[0];
    const int*   adjF    = (const int*)d_in[1];
    const int*   adjS    = (const int*)d_in[2];
    const float* W_enc1  = (const float*)d_in[3];
    const float* a_enc1  = (const float*)d_in[4];
    const float* W_enc2  = (const float*)d_in[5];
    const float* a_enc2  = (const float*)d_in[6];
    const float* W_dec1  = (const float*)d_in[7];
    const float* a_dec1  = (const float*)d_in[8];
    const float* W_dec2  = (const float*)d_in[9];
    const float* a_dec2  = (const float*)d_in[10];
    const float* w_omega = (const float*)d_in[11];
    const float* u_omega = (const float*)d_in[12];
    (void)in_sizes; (void)n_in; (void)out_size;

    float* out       = (float*)d_out;
    float* out_lat   = out;                                  // [4096, 64]
    float* out_recon = out + (size_t)NN * DOUT;              // [4096, 3000]
    float* out_corr  = out_recon + (size_t)NN * DIN;         // [4096, 64]
    float* out_alpha = out_corr + (size_t)NN * DOUT;         // [4096, 2]

    float *att, *bufA, *bufB, *bufC, *big, *embF, *embS, *sbuf, *vu, *part;
    cudaGetSymbolAddress((void**)&att,  g_att);
    cudaGetSymbolAddress((void**)&bufA, g_bufA);
    cudaGetSymbolAddress((void**)&bufB, g_bufB);
    cudaGetSymbolAddress((void**)&bufC, g_bufC);
    cudaGetSymbolAddress((void**)&big,  g_big);
    cudaGetSymbolAddress((void**)&embF, g_embF);
    cudaGetSymbolAddress((void**)&embS, g_embS);
    cudaGetSymbolAddress((void**)&sbuf, g_s);
    cudaGetSymbolAddress((void**)&vu,   g_vu);
    cudaGetSymbolAddress((void**)&part, g_part);

    float* sA1 = sbuf;          float* sB1 = sbuf + NN;
    float* sA2 = sbuf + 2 * NN; float* sB2 = sbuf + 3 * NN;

    // ===== encode(features, both views); layer-1 Wh shared =====
    run_gemm(X, W_enc1, bufA, NN, DHID, DIN, 0, 1);           // WH1 = X @ W_enc1
    scores_kernel<<<NN, 256>>>(bufA, DHID, a_enc1, sA1, sB1);
    encode_view(bufA, sA1, sB1, adjF, W_enc2, a_enc2, embF, att, bufB, bufC, part, sA2, sB2);
    encode_view(bufA, sA1, sB1, adjS, W_enc2, a_enc2, embS, att, bufB, bufC, part, sA2, sB2);

    // ===== attention fusion -> emb_latent, alpha =====
    vu_kernel<<<NN, 64>>>(embF, w_omega, u_omega, vu);
    vu_kernel<<<NN, 64>>>(embS, w_omega, u_omega, vu + NN);
    fuse_kernel<<<NN, 64>>>(embF, embS, vu, vu + NN, out_lat, out_alpha);

    // ===== decode (spatial adjacency) -> recon =====
    run_gemm(out_lat, W_dec1, bufC, NN, DHID, DOUT, 0, 1);    // WHd1
    scores_kernel<<<NN, 256>>>(bufC, DHID, a_dec1, sA2, sB2);
    att_kernel<<<NN, 256>>>(sA2, sB2, adjS, att);
    run_gemm(att, bufC, bufB, NN, DHID, NN, 1, 1);            // hd1 = elu(att@WHd1)
    run_gemm(bufB, W_dec2, big, NN, DIN, DHID, 0, 1);         // WHd2 [4096,3000]
    scores_kernel<<<NN, 256>>>(big, DIN, a_dec2, sA2, sB2);
    att_kernel<<<NN, 256>>>(sA2, sB2, adjS, att);
    run_gemm(att, big, out_recon, NN, DIN, NN, 1, 1);         // recon = elu(att@WHd2)

    // ===== corr = fuse(encode(recon, feat), encode(recon, spatial)) =====
    run_gemm(out_recon, W_enc1, bufA, NN, DHID, DIN, 0, 1);   // WHc1 (shared)
    scores_kernel<<<NN, 256>>>(bufA, DHID, a_enc1, sA1, sB1);
    encode_view(bufA, sA1, sB1, adjF, W_enc2, a_enc2, embF, att, bufB, bufC, part, sA2, sB2);
    encode_view(bufA, sA1, sB1, adjS, W_enc2, a_enc2, embS, att, bufB, bufC, part, sA2, sB2);
    vu_kernel<<<NN, 64>>>(embF, w_omega, u_omega, vu);
    vu_kernel<<<NN, 64>>>(embS, w_omega, u_omega, vu + NN);
    fuse_kernel<<<NN, 64>>>(embF, embS, vu, vu + NN, out_corr, (float*)0);
}

// round 4
// speedup vs baseline: 3.2108x; 3.2108x over previous
#include <cuda_runtime.h>
#include <cuda_fp16.h>
#include <math.h>
#include <stdint.h>

#define NN   4096
#define DIN  3000
#define DHID 512
#define DOUT 64

// ---------------- scratch (device globals; no runtime allocation) ----------------
__device__ float g_att [(size_t)NN * NN];
__device__ float g_bufA[(size_t)NN * DHID];
__device__ float g_bufB[(size_t)NN * DHID];
__device__ float g_bufC[(size_t)NN * DHID];
__device__ float g_big [(size_t)NN * DIN];
__device__ float g_embF[NN * DOUT];
__device__ float g_embS[NN * DOUT];
__device__ float g_s   [4 * NN];
__device__ float g_vu  [2 * NN];
__device__ float g_part[(size_t)8 * NN * DOUT];

// ---------------- fp16 tensor-core GEMM: C[M,N] = A[M,K] @ B[K,N] ----------------
// mma.sync.m16n8k16 (legacy HMMA path; valid on base sm_103 PTX target).
// CTA tile 128x128, BK=32, 256 threads = 8 warps in 4(M) x 2(N), warp tile 32x64.
// fp32 in global memory; converted to fp16 on the smem store. fp32 accumulate.
// SMEM rows padded to 40 halves -> conflict-free 32-bit fragment loads.
// gridDim.z = deterministic split-K (C becomes a partials buffer).
// Requires M % 128 == 0 (always 4096 here); N, K arbitrary.

#define BM 128
#define BN 128
#define BK 32
#define PAD 40   // halves per smem row

__global__ void __launch_bounds__(256)
hgemm(const float* __restrict__ A, const float* __restrict__ B,
      float* __restrict__ C, int M, int N, int K, int epi)
{
    __shared__ __align__(16) half As[2][BM][PAD];
    __shared__ __align__(16) half Bs[2][BN][PAD];   // Bs[n][k] = B[k][n] (col-major frag)

    const int tid = threadIdx.x;
    const int wid = tid >> 5;
    const int lane = tid & 31;
    const int g  = lane >> 2;      // groupID 0..7
    const int tg = lane & 3;       // thread-in-group 0..3
    const int wm = wid & 3;        // warp row 0..3  (32 rows each)
    const int wn = wid >> 2;       // warp col 0..1  (64 cols each)

    const int m0 = blockIdx.y * BM;
    const int n0 = blockIdx.x * BN;
    const int kChunk = K / gridDim.z;
    const int kBeg = blockIdx.z * kChunk;
    const int kEnd = kBeg + kChunk;
    C += (size_t)blockIdx.z * ((size_t)M * N);
    const int T = (kChunk + BK - 1) / BK;

    // ---- global-load thread mapping ----
    // A: 4 iters, each loads float4: row = (tid+256*i)>>3, cols = ((tid+256*i)&7)*4
    // B: n = tid&127 (coalesced), k = (tid>>7)*4 + 8*i, 4 strided floats each iter
    const int a_row = tid >> 1;              // reused pattern per iter below
    (void)a_row;
    const int b_n   = tid & 127;
    const int b_k0  = (tid >> 7) * 4;
    const bool b_nok = (n0 + b_n) < N;

    float4 pA[4];
    float  pB[16];

    auto gload = [&](int kt) {
        const int k0 = kBeg + kt * BK;
        const bool full = (k0 + BK <= kEnd);
#pragma unroll
        for (int i = 0; i < 4; i++) {
            const int idx = tid + 256 * i;
            const int row = idx >> 3;
            const int c4  = (idx & 7) * 4;
            const float* gp = A + (size_t)(m0 + row) * K + k0 + c4;
            if (full) {
                pA[i] = *(const float4*)gp;
            } else {
                const int kb = k0 + c4;
                pA[i].x = (kb + 0 < kEnd) ? gp[0] : 0.f;
                pA[i].y = (kb + 1 < kEnd) ? gp[1] : 0.f;
                pA[i].z = (kb + 2 < kEnd) ? gp[2] : 0.f;
                pA[i].w = (kb + 3 < kEnd) ? gp[3] : 0.f;
            }
        }
#pragma unroll
        for (int i = 0; i < 4; i++) {
            const int kk = b_k0 + 8 * i;
            const float* gp = B + (size_t)(k0 + kk) * N + n0 + b_n;
#pragma unroll
            for (int j = 0; j < 4; j++)
                pB[i * 4 + j] = (b_nok && (k0 + kk + j < kEnd)) ? gp[(size_t)j * N] : 0.f;
        }
    };
    auto sstore = [&](int b) {
#pragma unroll
        for (int i = 0; i < 4; i++) {
            const int idx = tid + 256 * i;
            const int row = idx >> 3;
            const int c4  = (idx & 7) * 4;
            half2 h0 = __floats2half2_rn(pA[i].x, pA[i].y);
            half2 h1 = __floats2half2_rn(pA[i].z, pA[i].w);
            *(half2*)&As[b][row][c4]     = h0;
            *(half2*)&As[b][row][c4 + 2] = h1;
        }
#pragma unroll
        for (int i = 0; i < 4; i++) {
            const int kk = b_k0 + 8 * i;
            half2 h0 = __floats2half2_rn(pB[i * 4 + 0], pB[i * 4 + 1]);
            half2 h1 = __floats2half2_rn(pB[i * 4 + 2], pB[i * 4 + 3]);
            *(half2*)&Bs[b][b_n][kk]     = h0;
            *(half2*)&Bs[b][b_n][kk + 2] = h1;
        }
    };

    float acc[2][8][4];
#pragma unroll
    for (int mf = 0; mf < 2; mf++)
#pragma unroll
        for (int nf = 0; nf < 8; nf++)
#pragma unroll
            for (int r = 0; r < 4; r++) acc[mf][nf][r] = 0.f;

    gload(0);
    sstore(0);
    __syncthreads();

    for (int kt = 0; kt < T; kt++) {
        const int b = kt & 1;
        if (kt + 1 < T) gload(kt + 1);   // LDGs in flight during MMA burst

        const uint32_t* uA = (const uint32_t*)&As[b][0][0];
        const uint32_t* uB = (const uint32_t*)&Bs[b][0][0];
        const int STRIDE = PAD / 2;  // 20 uint32 per row
#pragma unroll
        for (int ks = 0; ks < 2; ks++) {
            uint32_t af[2][4];
#pragma unroll
            for (int mf = 0; mf < 2; mf++) {
                const int rm = wm * 32 + mf * 16;
                af[mf][0] = uA[(rm + g)     * STRIDE + ks * 8 + tg];
                af[mf][1] = uA[(rm + g + 8) * STRIDE + ks * 8 + tg];
                af[mf][2] = uA[(rm + g)     * STRIDE + ks * 8 + tg + 4];
                af[mf][3] = uA[(rm + g + 8) * STRIDE + ks * 8 + tg + 4];
            }
            uint32_t bf[8][2];
#pragma unroll
            for (int nf = 0; nf < 8; nf++) {
                const int cn = wn * 64 + nf * 8;
                bf[nf][0] = uB[(cn + g) * STRIDE + ks * 8 + tg];
                bf[nf][1] = uB[(cn + g) * STRIDE + ks * 8 + tg + 4];
            }
#pragma unroll
            for (int mf = 0; mf < 2; mf++)
#pragma unroll
                for (int nf = 0; nf < 8; nf++) {
                    asm volatile(
                        "mma.sync.aligned.m16n8k16.row.col.f32.f16.f16.f32 "
                        "{%0,%1,%2,%3}, {%4,%5,%6,%7}, {%8,%9}, {%0,%1,%2,%3};"
                        : "+f"(acc[mf][nf][0]), "+f"(acc[mf][nf][1]),
                          "+f"(acc[mf][nf][2]), "+f"(acc[mf][nf][3])
                        : "r"(af[mf][0]), "r"(af[mf][1]), "r"(af[mf][2]), "r"(af[mf][3]),
                          "r"(bf[nf][0]), "r"(bf[nf][1]));
                }
        }

        if (kt + 1 < T) sstore(1 - b);
        __syncthreads();
    }

    // ---- epilogue: ELU optional, write fp32 ----
#pragma unroll
    for (int mf = 0; mf < 2; mf++) {
        const int r0 = m0 + wm * 32 + mf * 16 + g;
#pragma unroll
        for (int nf = 0; nf < 8; nf++) {
            const int c = n0 + wn * 64 + nf * 8 + 2 * tg;
            if (c < N) {
                float v0 = acc[mf][nf][0], v1 = acc[mf][nf][1];
                float v2 = acc[mf][nf][2], v3 = acc[mf][nf][3];
                if (epi) {
                    v0 = (v0 > 0.f) ? v0 : expm1f(v0);
                    v1 = (v1 > 0.f) ? v1 : expm1f(v1);
                    v2 = (v2 > 0.f) ? v2 : expm1f(v2);
                    v3 = (v3 > 0.f) ? v3 : expm1f(v3);
                }
                *(float2*)&C[(size_t)r0 * N + c]       = make_float2(v0, v1);
                *(float2*)&C[(size_t)(r0 + 8) * N + c] = make_float2(v2, v3);
            }
        }
    }
}

// sum split-K partials (fixed order => deterministic), optional ELU
__global__ void reduce_epi(const float* __restrict__ part, float* __restrict__ out,
                           int MNtot, int S, int epi)
{
    int t = blockIdx.x * blockDim.x + threadIdx.x;
    if (t >= MNtot) return;
    float v = 0.f;
    for (int s = 0; s < S; s++) v += part[(size_t)s * MNtot + t];
    if (epi) v = (v > 0.f) ? v : expm1f(v);
    out[t] = v;
}

// ---------------- GAT attention-score vectors: s1 = Wh@a[:f], s2 = Wh@a[f:] -------
__global__ void scores_kernel(const float* __restrict__ WH, int f,
                              const float* __restrict__ a,
                              float* __restrict__ s1, float* __restrict__ s2)
{
    __shared__ float r1[256], r2[256];
    const int i = blockIdx.x, tid = threadIdx.x;
    const float* row = WH + (size_t)i * f;
    float l1 = 0.f, l2 = 0.f;
    for (int c = tid; c < f; c += 256) {
        float w = row[c];
        l1 += w * a[c];
        l2 += w * a[c + f];
    }
    r1[tid] = l1; r2[tid] = l2;
    __syncthreads();
    for (int s = 128; s > 0; s >>= 1) {
        if (tid < s) { r1[tid] += r1[tid + s]; r2[tid] += r2[tid + s]; }
        __syncthreads();
    }
    if (tid == 0) { s1[i] = r1[0]; s2[i] = r2[0]; }
}

// ---------------- att[i,:] = softmax_j( adj[i,j]>0 ? lrelu(s1[i]+s2[j]) : -9e15 ) --
__global__ void att_kernel(const float* __restrict__ s1, const float* __restrict__ s2,
                           const int* __restrict__ adj, float* __restrict__ att)
{
    __shared__ float esh[NN];
    __shared__ float red[256];
    const int i = blockIdx.x;
    const int tid = threadIdx.x;
    const float s1i = s1[i];
    const int* arow = adj + (size_t)i * NN;

    float lmax = -3.4e38f;
    for (int j = tid; j < NN; j += 256) {
        float x = s1i + s2[j];
        x = (x > 0.f) ? x : 0.2f * x;
        float e = (arow[j] > 0) ? x : -9e15f;
        esh[j] = e;
        lmax = fmaxf(lmax, e);
    }
    red[tid] = lmax; __syncthreads();
    for (int s = 128; s > 0; s >>= 1) {
        if (tid < s) red[tid] = fmaxf(red[tid], red[tid + s]);
        __syncthreads();
    }
    const float m = red[0];
    __syncthreads();

    float lsum = 0.f;
    for (int j = tid; j < NN; j += 256) {
        float p = expf(esh[j] - m);
        esh[j] = p;
        lsum += p;
    }
    red[tid] = lsum; __syncthreads();
    for (int s = 128; s > 0; s >>= 1) {
        if (tid < s) red[tid] += red[tid + s];
        __syncthreads();
    }
    const float inv = 1.f / red[0];

    float* orow = att + (size_t)i * NN;
    for (int j = tid; j < NN; j += 256) orow[j] = esh[j] * inv;
}

// ---------------- fusion: vu[i] = tanh(emb[i]@w_omega) @ u_omega ------------------
__global__ void vu_kernel(const float* __restrict__ emb, const float* __restrict__ w,
                          const float* __restrict__ u, float* __restrict__ vu)
{
    __shared__ float er[64];
    __shared__ float red[64];
    const int i = blockIdx.x, k = threadIdx.x;
    er[k] = emb[(size_t)i * 64 + k];
    __syncthreads();
    float acc = 0.f;
#pragma unroll
    for (int d = 0; d < 64; d++) acc += er[d] * w[d * 64 + k];
    red[k] = tanhf(acc) * u[k];
    __syncthreads();
    for (int s = 32; s > 0; s >>= 1) {
        if (k < s) red[k] += red[k + s];
        __syncthreads();
    }
    if (k == 0) vu[i] = red[0];
}

__global__ void fuse_kernel(const float* __restrict__ e1, const float* __restrict__ e2,
                            const float* __restrict__ vu1, const float* __restrict__ vu2,
                            float* __restrict__ fused, float* __restrict__ alpha)
{
    const int i = blockIdx.x, d = threadIdx.x;
    float x0 = vu1[i] + 1e-6f, x1 = vu2[i] + 1e-6f;
    float m = fmaxf(x0, x1);
    float p0 = expf(x0 - m), p1 = expf(x1 - m);
    float inv = 1.f / (p0 + p1);
    float a0 = p0 * inv, a1 = p1 * inv;
    fused[(size_t)i * 64 + d] = a0 * e1[(size_t)i * 64 + d] + a1 * e2[(size_t)i * 64 + d];
    if (alpha != 0 && d < 2) alpha[(size_t)i * 2 + d] = (d == 0) ? a0 : a1;
}

// ---------------- host orchestration ----------------------------------------------
static inline void mm_run(const float* A, const float* B, float* C,
                          int M, int N, int K, int epi, int splits)
{
    dim3 grid((N + 127) / 128, M / 128, splits);
    hgemm<<<grid, 256>>>(A, B, C, M, N, K, epi);
}

static void encode_view(const float* WH1, const float* sA1, const float* sB1,
                        const int* adj, const float* W_enc2, const float* a_enc2,
                        float* emb_out,
                        float* att, float* bufB, float* bufC, float* part,
                        float* sA2, float* sB2)
{
    att_kernel<<<NN, 256>>>(sA1, sB1, adj, att);
    mm_run(att, WH1, bufB, NN, DHID, NN, 1, 1);                   // h1 = elu(att@WH1)
    mm_run(bufB, W_enc2, part, NN, DOUT, DHID, 0, 4);             // WH2 (split-K=4)
    reduce_epi<<<(NN * DOUT + 255) / 256, 256>>>(part, bufC, NN * DOUT, 4, 0);
    scores_kernel<<<NN, 256>>>(bufC, DOUT, a_enc2, sA2, sB2);
    att_kernel<<<NN, 256>>>(sA2, sB2, adj, att);
    mm_run(att, bufC, part, NN, DOUT, NN, 0, 8);                  // att@WH2 (split-K=8)
    reduce_epi<<<(NN * DOUT + 255) / 256, 256>>>(part, emb_out, NN * DOUT, 8, 1);
}

extern "C" void kernel_launch(void* const* d_in, const int* in_sizes, int n_in,
                              void* d_out, int out_size)
{
    const float* X       = (const float*)d_in[0];
    const int*   adjF    = (const int*)d_in[1];
    const int*   adjS    = (const int*)d_in[2];
    const float* W_enc1  = (const float*)d_in[3];
    const float* a_enc1  = (const float*)d_in[4];
    const float* W_enc2  = (const float*)d_in[5];
    const float* a_enc2  = (const float*)d_in[6];
    const float* W_dec1  = (const float*)d_in[7];
    const float* a_dec1  = (const float*)d_in[8];
    const float* W_dec2  = (const float*)d_in[9];
    const float* a_dec2  = (const float*)d_in[10];
    const float* w_omega = (const float*)d_in[11];
    const float* u_omega = (const float*)d_in[12];
    (void)in_sizes; (void)n_in; (void)out_size;

    float* out       = (float*)d_out;
    float* out_lat   = out;
    float* out_recon = out + (size_t)NN * DOUT;
    float* out_corr  = out_recon + (size_t)NN * DIN;
    float* out_alpha = out_corr + (size_t)NN * DOUT;

    float *att, *bufA, *bufB, *bufC, *big, *embF, *embS, *sbuf, *vu, *part;
    cudaGetSymbolAddress((void**)&att,  g_att);
    cudaGetSymbolAddress((void**)&bufA, g_bufA);
    cudaGetSymbolAddress((void**)&bufB, g_bufB);
    cudaGetSymbolAddress((void**)&bufC, g_bufC);
    cudaGetSymbolAddress((void**)&big,  g_big);
    cudaGetSymbolAddress((void**)&embF, g_embF);
    cudaGetSymbolAddress((void**)&embS, g_embS);
    cudaGetSymbolAddress((void**)&sbuf, g_s);
    cudaGetSymbolAddress((void**)&vu,   g_vu);
    cudaGetSymbolAddress((void**)&part, g_part);

    float* sA1 = sbuf;          float* sB1 = sbuf + NN;
    float* sA2 = sbuf + 2 * NN; float* sB2 = sbuf + 3 * NN;

    // ===== encode(features, both views); layer-1 Wh shared =====
    mm_run(X, W_enc1, bufA, NN, DHID, DIN, 0, 1);                 // WH1 = X @ W_enc1
    scores_kernel<<<NN, 256>>>(bufA, DHID, a_enc1, sA1, sB1);
    encode_view(bufA, sA1, sB1, adjF, W_enc2, a_enc2, embF, att, bufB, bufC, part, sA2, sB2);
    encode_view(bufA, sA1, sB1, adjS, W_enc2, a_enc2, embS, att, bufB, bufC, part, sA2, sB2);

    // ===== attention fusion -> emb_latent, alpha =====
    vu_kernel<<<NN, 64>>>(embF, w_omega, u_omega, vu);
    vu_kernel<<<NN, 64>>>(embS, w_omega, u_omega, vu + NN);
    fuse_kernel<<<NN, 64>>>(embF, embS, vu, vu + NN, out_lat, out_alpha);

    // ===== decode (spatial adjacency) -> recon =====
    mm_run(out_lat, W_dec1, bufC, NN, DHID, DOUT, 0, 1);          // WHd1
    scores_kernel<<<NN, 256>>>(bufC, DHID, a_dec1, sA2, sB2);
    att_kernel<<<NN, 256>>>(sA2, sB2, adjS, att);
    mm_run(att, bufC, bufB, NN, DHID, NN, 1, 1);                  // hd1 = elu(att@WHd1)
    mm_run(bufB, W_dec2, big, NN, DIN, DHID, 0, 1);               // WHd2 [4096,3000]
    scores_kernel<<<NN, 256>>>(big, DIN, a_dec2, sA2, sB2);
    att_kernel<<<NN, 256>>>(sA2, sB2, adjS, att);
    mm_run(att, big, out_recon, NN, DIN, NN, 1, 1);               // recon = elu(att@WHd2)

    // ===== corr = fuse(encode(recon, feat), encode(recon, spatial)) =====
    mm_run(out_recon, W_enc1, bufA, NN, DHID, DIN, 0, 1);         // WHc1 (shared)
    scores_kernel<<<NN, 256>>>(bufA, DHID, a_enc1, sA1, sB1);
    encode_view(bufA, sA1, sB1, adjF, W_enc2, a_enc2, embF, att, bufB, bufC, part, sA2, sB2);
    encode_view(bufA, sA1, sB1, adjS, W_enc2, a_enc2, embS, att, bufB, bufC, part, sA2, sB2);
    vu_kernel<<<NN, 64>>>(embF, w_omega, u_omega, vu);
    vu_kernel<<<NN, 64>>>(embS, w_omega, u_omega, vu + NN);
    fuse_kernel<<<NN, 64>>>(embF, embS, vu, vu + NN, out_corr, (float*)0);
}

// round 5
// speedup vs baseline: 5.4306x; 1.6913x over previous
#include <cuda_runtime.h>
#include <cuda_fp16.h>
#include <math.h>
#include <stdint.h>

#define NN   4096
#define DIN  3000
#define DHID 512
#define DOUT 64

// ---------------- scratch (device globals; no runtime allocation) ----------------
__device__ __half g_Xh   [(size_t)NN * DIN];
__device__ __half g_W1h  [(size_t)DIN * DHID];
__device__ __half g_W2h  [(size_t)DHID * DOUT];
__device__ __half g_Wd1h [(size_t)DOUT * DHID];
__device__ __half g_Wd2h [(size_t)DHID * DIN];
__device__ __half g_atth [(size_t)NN * NN];
__device__ __half g_wh1h [(size_t)NN * DHID];
__device__ __half g_h1h  [(size_t)NN * DHID];
__device__ __half g_whd1h[(size_t)NN * DHID];
__device__ __half g_wh2h [(size_t)NN * DOUT];
__device__ __half g_bigh [(size_t)NN * DIN];
__device__ __half g_reconh[(size_t)NN * DIN];
__device__ __half g_lath [(size_t)NN * DOUT];
__device__ uint32_t g_adjPF[(size_t)NN * (NN / 32)];
__device__ uint32_t g_adjPS[(size_t)NN * (NN / 32)];
__device__ float g_embF[NN * DOUT];
__device__ float g_embS[NN * DOUT];
__device__ float g_s   [4 * NN];
__device__ float g_vu  [2 * NN];
__device__ float g_part[(size_t)8 * NN * DOUT];

__device__ __forceinline__ uint32_t smem_u32(const void* p) {
    uint32_t a;
    asm("{ .reg .u64 t; cvta.to.shared.u64 t, %1; cvt.u32.u64 %0, t; }" : "=r"(a) : "l"(p));
    return a;
}

// ---------------- fp16 tensor-core GEMM with cp.async + ldmatrix ------------------
// C[M,N] = A[M,K] @ B[K,N]; A,B half row-major; fp32 accumulate.
// CTA 128x128, BK=64, 3-stage cp.async pipeline, 8 warps (4M x 2N), warp 32x64.
// Outputs: Cf (fp32, nullable) and/or Ch (half, nullable), optional ELU.
// gridDim.z = deterministic split-K; then Cf = partials buffer, gridDim.z slices.
// Requires M%128==0, K%8==0, N%8==0 (all shapes here satisfy this).
#define BM 128
#define BN 128
#define BK 64
#define STG 3
#define A_STAGE 16384
#define B_STAGE 16384
#define SMEM_BYTES (STG * (A_STAGE + B_STAGE))

__global__ void __launch_bounds__(256, 2)
hgemm(const __half* __restrict__ A, const __half* __restrict__ B,
      float* __restrict__ Cf, __half* __restrict__ Ch,
      int M, int N, int K, int epi)
{
    extern __shared__ char smem[];
    const uint32_t sA = smem_u32(smem);
    const uint32_t sB = sA + STG * A_STAGE;

    const int tid = threadIdx.x;
    const int wid = tid >> 5;
    const int lane = tid & 31;
    const int g  = lane >> 2;
    const int tg = lane & 3;
    const int wm = wid & 3;
    const int wn = wid >> 2;

    const int m0 = blockIdx.y * BM;
    const int n0 = blockIdx.x * BN;
    const int kChunk = K / gridDim.z;
    const int kBeg = blockIdx.z * kChunk;
    const int kEnd = kBeg + kChunk;
    if (Cf) Cf += (size_t)blockIdx.z * ((size_t)M * N);
    const int T = (kChunk + BK - 1) / BK;

    auto loadTile = [&](int kt, int slot) {
        const int k0 = kBeg + kt * BK;
#pragma unroll
        for (int i = 0; i < 4; i++) {
            const int id = tid + 256 * i;
            const int r = id >> 3, c = id & 7;
            const __half* src = A + (size_t)(m0 + r) * K + k0 + c * 8;
            int sz = (k0 + c * 8 < kEnd) ? 16 : 0;
            if (!sz) src = A;
            uint32_t dst = sA + slot * A_STAGE + r * 128 + ((c ^ (r & 7)) << 4);
            asm volatile("cp.async.cg.shared.global [%0], [%1], 16, %2;"
                         :: "r"(dst), "l"(src), "r"(sz));
        }
#pragma unroll
        for (int i = 0; i < 4; i++) {
            const int id = tid + 256 * i;
            const int r = id >> 4, c = id & 15;
            const __half* src = B + (size_t)(k0 + r) * N + n0 + c * 8;
            int sz = ((k0 + r < kEnd) && (n0 + c * 8 < N)) ? 16 : 0;
            if (!sz) src = B;
            uint32_t dst = sB + slot * B_STAGE + r * 256 + (((c & 8) | ((c & 7) ^ (r & 7))) << 4);
            asm volatile("cp.async.cg.shared.global [%0], [%1], 16, %2;"
                         :: "r"(dst), "l"(src), "r"(sz));
        }
    };

    float acc[2][8][4];
#pragma unroll
    for (int mf = 0; mf < 2; mf++)
#pragma unroll
        for (int nf = 0; nf < 8; nf++)
#pragma unroll
            for (int r = 0; r < 4; r++) acc[mf][nf][r] = 0.f;

    // prologue: stages 0,1
#pragma unroll
    for (int s = 0; s < STG - 1; s++) {
        if (s < T) loadTile(s, s);
        asm volatile("cp.async.commit_group;");
    }

    for (int kt = 0; kt < T; kt++) {
        asm volatile("cp.async.wait_group %0;" :: "n"(STG - 2));
        __syncthreads();
        if (kt + STG - 1 < T) loadTile(kt + STG - 1, (kt + STG - 1) % STG);
        asm volatile("cp.async.commit_group;");

        const int slot = kt % STG;
        const uint32_t baseA = sA + slot * A_STAGE;
        const uint32_t baseB = sB + slot * B_STAGE;
#pragma unroll
        for (int ks = 0; ks < 4; ks++) {
            uint32_t af[2][4];
#pragma unroll
            for (int mf = 0; mf < 2; mf++) {
                const int row = wm * 32 + mf * 16 + (lane & 15);
                const int c = ks * 2 + (lane >> 4);
                const uint32_t addr = baseA + row * 128 + ((c ^ (row & 7)) << 4);
                asm volatile("ldmatrix.sync.aligned.m8n8.x4.shared.b16 {%0,%1,%2,%3}, [%4];"
                             : "=r"(af[mf][0]), "=r"(af[mf][1]),
                               "=r"(af[mf][2]), "=r"(af[mf][3]) : "r"(addr));
            }
            uint32_t bf[8][2];
#pragma unroll
            for (int p = 0; p < 4; p++) {
                const int kr = ks * 16 + (lane & 15);
                const int cn = wn * 8 + p * 2 + (lane >> 4);
                const uint32_t addr = baseB + kr * 256 + (((cn & 8) | ((cn & 7) ^ (kr & 7))) << 4);
                uint32_t r0, r1, r2, r3;
                asm volatile("ldmatrix.sync.aligned.m8n8.x4.trans.shared.b16 {%0,%1,%2,%3}, [%4];"
                             : "=r"(r0), "=r"(r1), "=r"(r2), "=r"(r3) : "r"(addr));
                bf[p * 2][0] = r0; bf[p * 2][1] = r1;
                bf[p * 2 + 1][0] = r2; bf[p * 2 + 1][1] = r3;
            }
#pragma unroll
            for (int mf = 0; mf < 2; mf++)
#pragma unroll
                for (int nf = 0; nf < 8; nf++) {
                    asm volatile(
                        "mma.sync.aligned.m16n8k16.row.col.f32.f16.f16.f32 "
                        "{%0,%1,%2,%3}, {%4,%5,%6,%7}, {%8,%9}, {%0,%1,%2,%3};"
                        : "+f"(acc[mf][nf][0]), "+f"(acc[mf][nf][1]),
                          "+f"(acc[mf][nf][2]), "+f"(acc[mf][nf][3])
                        : "r"(af[mf][0]), "r"(af[mf][1]), "r"(af[mf][2]), "r"(af[mf][3]),
                          "r"(bf[nf][0]), "r"(bf[nf][1]));
                }
        }
    }

    // ---- epilogue ----
#pragma unroll
    for (int mf = 0; mf < 2; mf++) {
        const int r0 = m0 + wm * 32 + mf * 16 + g;
#pragma unroll
        for (int nf = 0; nf < 8; nf++) {
            const int c = n0 + wn * 64 + nf * 8 + 2 * tg;
            if (c < N) {
                float v0 = acc[mf][nf][0], v1 = acc[mf][nf][1];
                float v2 = acc[mf][nf][2], v3 = acc[mf][nf][3];
                if (epi) {
                    v0 = (v0 > 0.f) ? v0 : expm1f(v0);
                    v1 = (v1 > 0.f) ? v1 : expm1f(v1);
                    v2 = (v2 > 0.f) ? v2 : expm1f(v2);
                    v3 = (v3 > 0.f) ? v3 : expm1f(v3);
                }
                if (Cf) {
                    *(float2*)&Cf[(size_t)r0 * N + c]       = make_float2(v0, v1);
                    *(float2*)&Cf[(size_t)(r0 + 8) * N + c] = make_float2(v2, v3);
                }
                if (Ch) {
                    *(__half2*)&Ch[(size_t)r0 * N + c]       = __floats2half2_rn(v0, v1);
                    *(__half2*)&Ch[(size_t)(r0 + 8) * N + c] = __floats2half2_rn(v2, v3);
                }
            }
        }
    }
}

// ---------------- conversions & adjacency packing ---------------------------------
__global__ void f2h4(const float4* __restrict__ in, __half* __restrict__ out, int n4)
{
    int i = blockIdx.x * 256 + threadIdx.x;
    if (i >= n4) return;
    float4 v = in[i];
    *(__half2*)&out[i * 4]     = __floats2half2_rn(v.x, v.y);
    *(__half2*)&out[i * 4 + 2] = __floats2half2_rn(v.z, v.w);
}

__global__ void pack_adj(const int* __restrict__ adj, uint32_t* __restrict__ out, int nwords)
{
    int w = blockIdx.x * 256 + threadIdx.x;
    if (w >= nwords) return;
    const int* p = adj + (size_t)w * 32;
    uint32_t m = 0;
#pragma unroll
    for (int b = 0; b < 32; b++) m |= (p[b] > 0 ? 1u : 0u) << b;
    out[w] = m;
}

// sum split-K partials (fixed order => deterministic), optional ELU, f32/half outs
__global__ void reduce_epi(const float* __restrict__ part, float* __restrict__ outf,
                           __half* __restrict__ outh, int MNtot, int S, int epi)
{
    int t = blockIdx.x * blockDim.x + threadIdx.x;
    if (t >= MNtot) return;
    float v = 0.f;
    for (int s = 0; s < S; s++) v += part[(size_t)s * MNtot + t];
    if (epi) v = (v > 0.f) ? v : expm1f(v);
    if (outf) outf[t] = v;
    if (outh) outh[t] = __float2half_rn(v);
}

// ---------------- GAT score vectors: s1 = Wh@a[:f], s2 = Wh@a[f:] (Wh half) -------
__global__ void scores_kernel(const __half* __restrict__ WH, int f,
                              const float* __restrict__ a,
                              float* __restrict__ s1, float* __restrict__ s2)
{
    __shared__ float r1[256], r2[256];
    const int i = blockIdx.x, tid = threadIdx.x;
    const __half* row = WH + (size_t)i * f;
    float l1 = 0.f, l2 = 0.f;
    for (int c = tid; c < f; c += 256) {
        float w = __half2float(row[c]);
        l1 += w * a[c];
        l2 += w * a[c + f];
    }
    r1[tid] = l1; r2[tid] = l2;
    __syncthreads();
    for (int s = 128; s > 0; s >>= 1) {
        if (tid < s) { r1[tid] += r1[tid + s]; r2[tid] += r2[tid + s]; }
        __syncthreads();
    }
    if (tid == 0) { s1[i] = r1[0]; s2[i] = r2[0]; }
}

// ---------------- att[i,:] = softmax_j(masked lrelu(s1_i + s2_j)), half out -------
__global__ void att_kernel(const float* __restrict__ s1, const float* __restrict__ s2,
                           const uint32_t* __restrict__ adjp, __half* __restrict__ att)
{
    __shared__ float esh[NN];
    __shared__ float red[256];
    const int i = blockIdx.x;
    const int tid = threadIdx.x;
    const float s1i = s1[i];
    const uint32_t* arow = adjp + (size_t)i * (NN / 32);

    float lmax = -3.4e38f;
    for (int j = tid; j < NN; j += 256) {
        float x = s1i + s2[j];
        x = (x > 0.f) ? x : 0.2f * x;
        uint32_t w = arow[j >> 5];
        float e = ((w >> (j & 31)) & 1u) ? x : -9e15f;
        esh[j] = e;
        lmax = fmaxf(lmax, e);
    }
    red[tid] = lmax; __syncthreads();
    for (int s = 128; s > 0; s >>= 1) {
        if (tid < s) red[tid] = fmaxf(red[tid], red[tid + s]);
        __syncthreads();
    }
    const float m = red[0];
    __syncthreads();

    float lsum = 0.f;
    for (int j = tid; j < NN; j += 256) {
        float p = expf(esh[j] - m);
        esh[j] = p;
        lsum += p;
    }
    red[tid] = lsum; __syncthreads();
    for (int s = 128; s > 0; s >>= 1) {
        if (tid < s) red[tid] += red[tid + s];
        __syncthreads();
    }
    const float inv = 1.f / red[0];

    __half* orow = att + (size_t)i * NN;
    for (int j = tid; j < NN; j += 256) orow[j] = __float2half_rn(esh[j] * inv);
}

// ---------------- fusion ----------------------------------------------------------
__global__ void vu_kernel(const float* __restrict__ emb, const float* __restrict__ w,
                          const float* __restrict__ u, float* __restrict__ vu)
{
    __shared__ float er[64];
    __shared__ float red[64];
    const int i = blockIdx.x, k = threadIdx.x;
    er[k] = emb[(size_t)i * 64 + k];
    __syncthreads();
    float acc = 0.f;
#pragma unroll
    for (int d = 0; d < 64; d++) acc += er[d] * w[d * 64 + k];
    red[k] = tanhf(acc) * u[k];
    __syncthreads();
    for (int s = 32; s > 0; s >>= 1) {
        if (k < s) red[k] += red[k + s];
        __syncthreads();
    }
    if (k == 0) vu[i] = red[0];
}

__global__ void fuse_kernel(const float* __restrict__ e1, const float* __restrict__ e2,
                            const float* __restrict__ vu1, const float* __restrict__ vu2,
                            float* __restrict__ fused, __half* __restrict__ fusedh,
                            float* __restrict__ alpha)
{
    const int i = blockIdx.x, d = threadIdx.x;
    float x0 = vu1[i] + 1e-6f, x1 = vu2[i] + 1e-6f;
    float m = fmaxf(x0, x1);
    float p0 = expf(x0 - m), p1 = expf(x1 - m);
    float inv = 1.f / (p0 + p1);
    float a0 = p0 * inv, a1 = p1 * inv;
    float v = a0 * e1[(size_t)i * 64 + d] + a1 * e2[(size_t)i * 64 + d];
    fused[(size_t)i * 64 + d] = v;
    if (fusedh) fusedh[(size_t)i * 64 + d] = __float2half_rn(v);
    if (alpha != 0 && d < 2) alpha[(size_t)i * 2 + d] = (d == 0) ? a0 : a1;
}

// ---------------- host orchestration ----------------------------------------------
static inline void mm(const __half* A, const __half* B, float* Cf, __half* Ch,
                      int M, int N, int K, int epi, int splits)
{
    dim3 grid((N + 127) / 128, M / 128, splits);
    hgemm<<<grid, 256, SMEM_BYTES>>>(A, B, Cf, Ch, M, N, K, epi);
}

static void encode_view(const __half* WH1h, const float* sA1, const float* sB1,
                        const uint32_t* adjp, const __half* W2h, const float* a_enc2,
                        float* emb_out,
                        __half* atth, __half* h1h, __half* wh2h, float* part,
                        float* sA2, float* sB2)
{
    att_kernel<<<NN, 256>>>(sA1, sB1, adjp, atth);
    mm(atth, WH1h, 0, h1h, NN, DHID, NN, 1, 1);                   // h1 = elu(att@WH1)
    mm(h1h, W2h, part, 0, NN, DOUT, DHID, 0, 4);                  // WH2 (split-K=4)
    reduce_epi<<<(NN * DOUT + 255) / 256, 256>>>(part, 0, wh2h, NN * DOUT, 4, 0);
    scores_kernel<<<NN, 256>>>(wh2h, DOUT, a_enc2, sA2, sB2);
    att_kernel<<<NN, 256>>>(sA2, sB2, adjp, atth);
    mm(atth, wh2h, part, 0, NN, DOUT, NN, 0, 8);                  // att@WH2 (split-K=8)
    reduce_epi<<<(NN * DOUT + 255) / 256, 256>>>(part, emb_out, 0, NN * DOUT, 8, 1);
}

extern "C" void kernel_launch(void* const* d_in, const int* in_sizes, int n_in,
                              void* d_out, int out_size)
{
    const float* X       = (const float*)d_in[0];
    const int*   adjF    = (const int*)d_in[1];
    const int*   adjS    = (const int*)d_in[2];
    const float* W_enc1  = (const float*)d_in[3];
    const float* a_enc1  = (const float*)d_in[4];
    const float* W_enc2  = (const float*)d_in[5];
    const float* a_enc2  = (const float*)d_in[6];
    const float* W_dec1  = (const float*)d_in[7];
    const float* a_dec1  = (const float*)d_in[8];
    const float* W_dec2  = (const float*)d_in[9];
    const float* a_dec2  = (const float*)d_in[10];
    const float* w_omega = (const float*)d_in[11];
    const float* u_omega = (const float*)d_in[12];
    (void)in_sizes; (void)n_in; (void)out_size;

    cudaFuncSetAttribute(hgemm, cudaFuncAttributeMaxDynamicSharedMemorySize, SMEM_BYTES);

    float* out       = (float*)d_out;
    float* out_lat   = out;
    float* out_recon = out + (size_t)NN * DOUT;
    float* out_corr  = out_recon + (size_t)NN * DIN;
    float* out_alpha = out_corr + (size_t)NN * DOUT;

    __half *Xh, *W1h, *W2h, *Wd1h, *Wd2h, *atth, *wh1h, *h1h, *whd1h, *wh2h;
    __half *bigh, *reconh, *lath;
    uint32_t *adjPF, *adjPS;
    float *embF, *embS, *sbuf, *vu, *part;
    cudaGetSymbolAddress((void**)&Xh,    g_Xh);
    cudaGetSymbolAddress((void**)&W1h,   g_W1h);
    cudaGetSymbolAddress((void**)&W2h,   g_W2h);
    cudaGetSymbolAddress((void**)&Wd1h,  g_Wd1h);
    cudaGetSymbolAddress((void**)&Wd2h,  g_Wd2h);
    cudaGetSymbolAddress((void**)&atth,  g_atth);
    cudaGetSymbolAddress((void**)&wh1h,  g_wh1h);
    cudaGetSymbolAddress((void**)&h1h,   g_h1h);
    cudaGetSymbolAddress((void**)&whd1h, g_whd1h);
    cudaGetSymbolAddress((void**)&wh2h,  g_wh2h);
    cudaGetSymbolAddress((void**)&bigh,  g_bigh);
    cudaGetSymbolAddress((void**)&reconh,g_reconh);
    cudaGetSymbolAddress((void**)&lath,  g_lath);
    cudaGetSymbolAddress((void**)&adjPF, g_adjPF);
    cudaGetSymbolAddress((void**)&adjPS, g_adjPS);
    cudaGetSymbolAddress((void**)&embF,  g_embF);
    cudaGetSymbolAddress((void**)&embS,  g_embS);
    cudaGetSymbolAddress((void**)&sbuf,  g_s);
    cudaGetSymbolAddress((void**)&vu,    g_vu);
    cudaGetSymbolAddress((void**)&part,  g_part);

    float* sA1 = sbuf;          float* sB1 = sbuf + NN;
    float* sA2 = sbuf + 2 * NN; float* sB2 = sbuf + 3 * NN;

    // ===== one-time conversions =====
    f2h4<<<(NN * DIN / 4 + 255) / 256, 256>>>((const float4*)X, Xh, NN * DIN / 4);
    f2h4<<<(DIN * DHID / 4 + 255) / 256, 256>>>((const float4*)W_enc1, W1h, DIN * DHID / 4);
    f2h4<<<(DHID * DOUT / 4 + 255) / 256, 256>>>((const float4*)W_enc2, W2h, DHID * DOUT / 4);
    f2h4<<<(DOUT * DHID / 4 + 255) / 256, 256>>>((const float4*)W_dec1, Wd1h, DOUT * DHID / 4);
    f2h4<<<(DHID * DIN / 4 + 255) / 256, 256>>>((const float4*)W_dec2, Wd2h, DHID * DIN / 4);
    pack_adj<<<(NN * NN / 32 + 255) / 256, 256>>>(adjF, adjPF, NN * NN / 32);
    pack_adj<<<(NN * NN / 32 + 255) / 256, 256>>>(adjS, adjPS, NN * NN / 32);

    // ===== encode(features, both views); layer-1 Wh shared =====
    mm(Xh, W1h, 0, wh1h, NN, DHID, DIN, 0, 1);                    // WH1 = X @ W_enc1
    scores_kernel<<<NN, 256>>>(wh1h, DHID, a_enc1, sA1, sB1);
    encode_view(wh1h, sA1, sB1, adjPF, W2h, a_enc2, embF, atth, h1h, wh2h, part, sA2, sB2);
    encode_view(wh1h, sA1, sB1, adjPS, W2h, a_enc2, embS, atth, h1h, wh2h, part, sA2, sB2);

    // ===== attention fusion -> emb_latent, alpha =====
    vu_kernel<<<NN, 64>>>(embF, w_omega, u_omega, vu);
    vu_kernel<<<NN, 64>>>(embS, w_omega, u_omega, vu + NN);
    fuse_kernel<<<NN, 64>>>(embF, embS, vu, vu + NN, out_lat, lath, out_alpha);

    // ===== decode (spatial adjacency) -> recon =====
    mm(lath, Wd1h, 0, whd1h, NN, DHID, DOUT, 0, 1);               // WHd1
    scores_kernel<<<NN, 256>>>(whd1h, DHID, a_dec1, sA2, sB2);
    att_kernel<<<NN, 256>>>(sA2, sB2, adjPS, atth);
    mm(atth, whd1h, 0, h1h, NN, DHID, NN, 1, 1);                  // hd1 = elu(att@WHd1)
    mm(h1h, Wd2h, 0, bigh, NN, DIN, DHID, 0, 1);                  // WHd2 [4096,3000]
    scores_kernel<<<NN, 256>>>(bigh, DIN, a_dec2, sA2, sB2);
    att_kernel<<<NN, 256>>>(sA2, sB2, adjPS, atth);
    mm(atth, bigh, out_recon, reconh, NN, DIN, NN, 1, 1);         // recon = elu(att@WHd2)

    // ===== corr = fuse(encode(recon, feat), encode(recon, spatial)) =====
    mm(reconh, W1h, 0, wh1h, NN, DHID, DIN, 0, 1);                // WHc1 (shared)
    scores_kernel<<<NN, 256>>>(wh1h, DHID, a_enc1, sA1, sB1);
    encode_view(wh1h, sA1, sB1, adjPF, W2h, a_enc2, embF, atth, h1h, wh2h, part, sA2, sB2);
    encode_view(wh1h, sA1, sB1, adjPS, W2h, a_enc2, embS, atth, h1h, wh2h, part, sA2, sB2);
    vu_kernel<<<NN, 64>>>(embF, w_omega, u_omega, vu);
    vu_kernel<<<NN, 64>>>(embS, w_omega, u_omega, vu + NN);
    fuse_kernel<<<NN, 64>>>(embF, embS, vu, vu + NN, out_corr, (__half*)0, (float*)0);
}

// round 6
// speedup vs baseline: 6.3832x; 1.1754x over previous
#include <cuda_runtime.h>
#include <cuda_fp16.h>
#include <math.h>
#include <stdint.h>

#define NN   4096
#define DIN  3000
#define DHID 512
#define DOUT 64

// ---------------- scratch (device globals; no runtime allocation) ----------------
__device__ __half g_Xh    [(size_t)NN * DIN];
__device__ __half g_W1h   [(size_t)DIN * DHID];
__device__ __half g_W2h   [(size_t)DHID * DOUT];
__device__ __half g_Wd1h  [(size_t)DOUT * DHID];
__device__ __half g_Wd2h  [(size_t)DHID * DIN];
__device__ __half g_att2h [(size_t)2 * NN * NN];     // batched att (both views)
__device__ __half g_wh1h  [(size_t)NN * DHID];
__device__ __half g_h1h2  [(size_t)2 * NN * DHID];   // batched h1
__device__ __half g_whd1h [(size_t)NN * DHID];
__device__ __half g_wh2h2 [(size_t)2 * NN * DOUT];   // batched wh2
__device__ __half g_bigh  [(size_t)NN * DIN];
__device__ __half g_reconh[(size_t)NN * DIN];
__device__ __half g_lath  [(size_t)NN * DOUT];
__device__ uint32_t g_adjPF[(size_t)NN * (NN / 32)];
__device__ uint32_t g_adjPS[(size_t)NN * (NN / 32)];
__device__ float g_embF[NN * DOUT];
__device__ float g_embS[NN * DOUT];
__device__ float g_s   [8 * NN];       // sA1,sB1 (NN each) + sA2,sB2 (2NN each)
__device__ float g_vu  [2 * NN];
__device__ float g_part[(size_t)2 * NN * DHID];  // split-K partials (max 4M floats)

__device__ __forceinline__ uint32_t smem_u32(const void* p) {
    uint32_t a;
    asm("{ .reg .u64 t; cvta.to.shared.u64 t, %1; cvt.u32.u64 %0, t; }" : "=r"(a) : "l"(p));
    return a;
}

// ---------------- fp16 tensor-core GEMM with cp.async + ldmatrix ------------------
// C[M,N] = A[M,K] @ B[K,N]; half in, fp32 accumulate. Template BN_=128 or 64.
// CTA BMx BN_, BK=64, 3-stage cp.async, 8 warps; warp tile 32 x (BN_/2).
// gridDim.z = deterministic split-K (64-aligned ranges); then Cf = partials.
// Requires M%128==0, N%8==0.
#define BM 128
#define BK 64
#define STG 3
#define A_STAGE 16384

template<int BN_>
__global__ void __launch_bounds__(256, 2)
hgemm(const __half* __restrict__ A, const __half* __restrict__ B,
      float* __restrict__ Cf, __half* __restrict__ Ch,
      int M, int N, int K, int epi)
{
    constexpr int CH = BN_ / 8;          // 16B chunks per B row
    constexpr int NF = BN_ / 16;         // n-fragments per warp
    constexpr int B_STAGE = 64 * BN_ * 2;
    extern __shared__ char smem[];
    const uint32_t sA = smem_u32(smem);
    const uint32_t sB = sA + STG * A_STAGE;

    const int tid = threadIdx.x;
    const int wid = tid >> 5;
    const int lane = tid & 31;
    const int g  = lane >> 2;
    const int tg = lane & 3;
    const int wm = wid & 3;
    const int wn = wid >> 2;

    const int m0 = blockIdx.y * BM;
    const int n0 = blockIdx.x * BN_;
    const int gz = gridDim.z;
    const int kChunkR = (((K + gz - 1) / gz) + 63) & ~63;
    const int kBeg = blockIdx.z * kChunkR;
    const int kEnd = min(kBeg + kChunkR, K);
    if (Cf) Cf += (size_t)blockIdx.z * ((size_t)M * N);
    const int T = (kEnd > kBeg) ? ((kEnd - kBeg + BK - 1) / BK) : 0;

    auto loadTile = [&](int kt, int slot) {
        const int k0 = kBeg + kt * BK;
#pragma unroll
        for (int i = 0; i < 4; i++) {
            const int id = tid + 256 * i;
            const int r = id >> 3, c = id & 7;
            const __half* src = A + (size_t)(m0 + r) * K + k0 + c * 8;
            int sz = (k0 + c * 8 < kEnd) ? 16 : 0;
            if (!sz) src = A;
            uint32_t dst = sA + slot * A_STAGE + r * 128 + ((c ^ (r & 7)) << 4);
            asm volatile("cp.async.cg.shared.global [%0], [%1], 16, %2;"
                         :: "r"(dst), "l"(src), "r"(sz));
        }
#pragma unroll
        for (int i = 0; i < (64 * CH) / 256; i++) {
            const int id = tid + 256 * i;
            const int r = id / CH, c = id % CH;
            const __half* src = B + (size_t)(k0 + r) * N + n0 + c * 8;
            int sz = ((k0 + r < kEnd) && (n0 + c * 8 < N)) ? 16 : 0;
            if (!sz) src = B;
            const int swz = (c & ~7) | ((c & 7) ^ (r & 7));
            uint32_t dst = sB + slot * B_STAGE + r * (CH * 16) + (swz << 4);
            asm volatile("cp.async.cg.shared.global [%0], [%1], 16, %2;"
                         :: "r"(dst), "l"(src), "r"(sz));
        }
    };

    float acc[2][NF][4];
#pragma unroll
    for (int mf = 0; mf < 2; mf++)
#pragma unroll
        for (int nf = 0; nf < NF; nf++)
#pragma unroll
            for (int r = 0; r < 4; r++) acc[mf][nf][r] = 0.f;

#pragma unroll
    for (int s = 0; s < STG - 1; s++) {
        if (s < T) loadTile(s, s);
        asm volatile("cp.async.commit_group;");
    }

    for (int kt = 0; kt < T; kt++) {
        asm volatile("cp.async.wait_group %0;" :: "n"(STG - 2));
        __syncthreads();
        if (kt + STG - 1 < T) loadTile(kt + STG - 1, (kt + STG - 1) % STG);
        asm volatile("cp.async.commit_group;");

        const int slot = kt % STG;
        const uint32_t baseA = sA + slot * A_STAGE;
        const uint32_t baseB = sB + slot * B_STAGE;
#pragma unroll
        for (int ks = 0; ks < 4; ks++) {
            uint32_t af[2][4];
#pragma unroll
            for (int mf = 0; mf < 2; mf++) {
                const int row = wm * 32 + mf * 16 + (lane & 15);
                const int c = ks * 2 + (lane >> 4);
                const uint32_t addr = baseA + row * 128 + ((c ^ (row & 7)) << 4);
                asm volatile("ldmatrix.sync.aligned.m8n8.x4.shared.b16 {%0,%1,%2,%3}, [%4];"
                             : "=r"(af[mf][0]), "=r"(af[mf][1]),
                               "=r"(af[mf][2]), "=r"(af[mf][3]) : "r"(addr));
            }
            uint32_t bf[NF][2];
#pragma unroll
            for (int p = 0; p < NF / 2; p++) {
                const int kr = ks * 16 + (lane & 15);
                const int cn = wn * NF + p * 2 + (lane >> 4);
                const int swz = (cn & ~7) | ((cn & 7) ^ (kr & 7));
                const uint32_t addr = baseB + kr * (CH * 16) + (swz << 4);
                uint32_t r0, r1, r2, r3;
                asm volatile("ldmatrix.sync.aligned.m8n8.x4.trans.shared.b16 {%0,%1,%2,%3}, [%4];"
                             : "=r"(r0), "=r"(r1), "=r"(r2), "=r"(r3) : "r"(addr));
                bf[p * 2][0] = r0; bf[p * 2][1] = r1;
                bf[p * 2 + 1][0] = r2; bf[p * 2 + 1][1] = r3;
            }
#pragma unroll
            for (int mf = 0; mf < 2; mf++)
#pragma unroll
                for (int nf = 0; nf < NF; nf++) {
                    asm volatile(
                        "mma.sync.aligned.m16n8k16.row.col.f32.f16.f16.f32 "
                        "{%0,%1,%2,%3}, {%4,%5,%6,%7}, {%8,%9}, {%0,%1,%2,%3};"
                        : "+f"(acc[mf][nf][0]), "+f"(acc[mf][nf][1]),
                          "+f"(acc[mf][nf][2]), "+f"(acc[mf][nf][3])
                        : "r"(af[mf][0]), "r"(af[mf][1]), "r"(af[mf][2]), "r"(af[mf][3]),
                          "r"(bf[nf][0]), "r"(bf[nf][1]));
                }
        }
    }

#pragma unroll
    for (int mf = 0; mf < 2; mf++) {
        const int r0 = m0 + wm * 32 + mf * 16 + g;
#pragma unroll
        for (int nf = 0; nf < NF; nf++) {
            const int c = n0 + wn * (NF * 8) + nf * 8 + 2 * tg;
            if (c < N) {
                float v0 = acc[mf][nf][0], v1 = acc[mf][nf][1];
                float v2 = acc[mf][nf][2], v3 = acc[mf][nf][3];
                if (epi) {
                    v0 = (v0 > 0.f) ? v0 : expm1f(v0);
                    v1 = (v1 > 0.f) ? v1 : expm1f(v1);
                    v2 = (v2 > 0.f) ? v2 : expm1f(v2);
                    v3 = (v3 > 0.f) ? v3 : expm1f(v3);
                }
                if (Cf) {
                    *(float2*)&Cf[(size_t)r0 * N + c]       = make_float2(v0, v1);
                    *(float2*)&Cf[(size_t)(r0 + 8) * N + c] = make_float2(v2, v3);
                }
                if (Ch) {
                    *(__half2*)&Ch[(size_t)r0 * N + c]       = __floats2half2_rn(v0, v1);
                    *(__half2*)&Ch[(size_t)(r0 + 8) * N + c] = __floats2half2_rn(v2, v3);
                }
            }
        }
    }
}

// ---------------- conversions & adjacency packing ---------------------------------
__global__ void f2h4(const float4* __restrict__ in, __half* __restrict__ out, int n4)
{
    int i = blockIdx.x * 256 + threadIdx.x;
    if (i >= n4) return;
    float4 v = in[i];
    *(__half2*)&out[i * 4]     = __floats2half2_rn(v.x, v.y);
    *(__half2*)&out[i * 4 + 2] = __floats2half2_rn(v.z, v.w);
}

__global__ void pack_adj(const int* __restrict__ adj, uint32_t* __restrict__ out, int nwords)
{
    int w = blockIdx.x * 256 + threadIdx.x;
    if (w >= nwords) return;
    const int* p = adj + (size_t)w * 32;
    uint32_t m = 0;
#pragma unroll
    for (int b = 0; b < 32; b++) m |= (p[b] > 0 ? 1u : 0u) << b;
    out[w] = m;
}

// sum split-K partials (fixed order => deterministic), optional ELU, f32/half outs
__global__ void reduce_epi(const float* __restrict__ part, float* __restrict__ outf,
                           __half* __restrict__ outh, int MNtot, int S, int epi)
{
    int t = blockIdx.x * blockDim.x + threadIdx.x;
    if (t >= MNtot) return;
    float v = 0.f;
    for (int s = 0; s < S; s++) v += part[(size_t)s * MNtot + t];
    if (epi) v = (v > 0.f) ? v : expm1f(v);
    if (outf) outf[t] = v;
    if (outh) outh[t] = __float2half_rn(v);
}

// ---------------- GAT score vectors: s1 = Wh@a[:f], s2 = Wh@a[f:] (Wh half) -------
__global__ void scores_kernel(const __half* __restrict__ WH, int f,
                              const float* __restrict__ a,
                              float* __restrict__ s1, float* __restrict__ s2)
{
    __shared__ float r1[256], r2[256];
    const int i = blockIdx.x, tid = threadIdx.x;
    const __half* row = WH + (size_t)i * f;
    float l1 = 0.f, l2 = 0.f;
    for (int c = tid; c < f; c += 256) {
        float w = __half2float(row[c]);
        l1 += w * a[c];
        l2 += w * a[c + f];
    }
    r1[tid] = l1; r2[tid] = l2;
    __syncthreads();
    for (int s = 128; s > 0; s >>= 1) {
        if (tid < s) { r1[tid] += r1[tid + s]; r2[tid] += r2[tid + s]; }
        __syncthreads();
    }
    if (tid == 0) { s1[i] = r1[0]; s2[i] = r2[0]; }
}

// ---------------- att row softmax (optionally batched over 2 views) ---------------
// Row r: i = r & 4095, view = r >> 12. adj = view? adjB : adjA.
// per_view: s1/s2 arrays have a separate NN-block per view.
__global__ void att_kernel(const float* __restrict__ s1, const float* __restrict__ s2,
                           const uint32_t* __restrict__ adjA, const uint32_t* __restrict__ adjB,
                           __half* __restrict__ att, int per_view)
{
    __shared__ float red[8];
    const int r = blockIdx.x;
    const int i = r & (NN - 1);
    const int view = r >> 12;
    const uint32_t* arow = (view ? adjB : adjA) + (size_t)i * (NN / 32);
    const int vb = per_view ? (view << 12) : 0;
    const float s1i = s1[vb + i];
    const float* s2p = s2 + vb;
    const int tid = threadIdx.x;
    const int base = tid * 16;
    const uint32_t bits = (arow[tid >> 1] >> ((tid & 1) * 16)) & 0xFFFFu;

    float e[16];
    float lmax = -3.4e38f;
#pragma unroll
    for (int u = 0; u < 16; u += 4) {
        float4 s4 = *(const float4*)&s2p[base + u];
        float xs[4] = {s4.x, s4.y, s4.z, s4.w};
#pragma unroll
        for (int q = 0; q < 4; q++) {
            float x = s1i + xs[q];
            x = (x > 0.f) ? x : 0.2f * x;
            float ev = ((bits >> (u + q)) & 1u) ? x : -9e15f;
            e[u + q] = ev;
            lmax = fmaxf(lmax, ev);
        }
    }
#pragma unroll
    for (int o = 16; o; o >>= 1) lmax = fmaxf(lmax, __shfl_xor_sync(~0u, lmax, o));
    if ((tid & 31) == 0) red[tid >> 5] = lmax;
    __syncthreads();
    float m = red[0];
#pragma unroll
    for (int w = 1; w < 8; w++) m = fmaxf(m, red[w]);
    __syncthreads();

    float lsum = 0.f;
#pragma unroll
    for (int u = 0; u < 16; u++) { e[u] = __expf(e[u] - m); lsum += e[u]; }
#pragma unroll
    for (int o = 16; o; o >>= 1) lsum += __shfl_xor_sync(~0u, lsum, o);
    if ((tid & 31) == 0) red[tid >> 5] = lsum;
    __syncthreads();
    float tot = 0.f;
#pragma unroll
    for (int w = 0; w < 8; w++) tot += red[w];
    const float inv = 1.f / tot;

    __half2 h[8];
#pragma unroll
    for (int u = 0; u < 8; u++)
        h[u] = __floats2half2_rn(e[2 * u] * inv, e[2 * u + 1] * inv);
    __half* orow = att + (size_t)r * NN + base;
    *(uint4*)orow       = *(uint4*)&h[0];
    *(uint4*)(orow + 8) = *(uint4*)&h[4];
}

// ---------------- fusion ----------------------------------------------------------
__global__ void vu_kernel(const float* __restrict__ emb, const float* __restrict__ w,
                          const float* __restrict__ u, float* __restrict__ vu)
{
    __shared__ float er[64];
    __shared__ float red[64];
    const int i = blockIdx.x, k = threadIdx.x;
    er[k] = emb[(size_t)i * 64 + k];
    __syncthreads();
    float acc = 0.f;
#pragma unroll
    for (int d = 0; d < 64; d++) acc += er[d] * w[d * 64 + k];
    red[k] = tanhf(acc) * u[k];
    __syncthreads();
    for (int s = 32; s > 0; s >>= 1) {
        if (k < s) red[k] += red[k + s];
        __syncthreads();
    }
    if (k == 0) vu[i] = red[0];
}

__global__ void fuse_kernel(const float* __restrict__ e1, const float* __restrict__ e2,
                            const float* __restrict__ vu1, const float* __restrict__ vu2,
                            float* __restrict__ fused, __half* __restrict__ fusedh,
                            float* __restrict__ alpha)
{
    const int i = blockIdx.x, d = threadIdx.x;
    float x0 = vu1[i] + 1e-6f, x1 = vu2[i] + 1e-6f;
    float m = fmaxf(x0, x1);
    float p0 = expf(x0 - m), p1 = expf(x1 - m);
    float inv = 1.f / (p0 + p1);
    float a0 = p0 * inv, a1 = p1 * inv;
    float v = a0 * e1[(size_t)i * 64 + d] + a1 * e2[(size_t)i * 64 + d];
    fused[(size_t)i * 64 + d] = v;
    if (fusedh) fusedh[(size_t)i * 64 + d] = __float2half_rn(v);
    if (alpha != 0 && d < 2) alpha[(size_t)i * 2 + d] = (d == 0) ? a0 : a1;
}

// ---------------- host orchestration ----------------------------------------------
static inline void mm128(const __half* A, const __half* B, float* Cf, __half* Ch,
                         int M, int N, int K, int epi, int splits)
{
    dim3 grid((N + 127) / 128, M / 128, splits);
    hgemm<128><<<grid, 256, STG * (A_STAGE + 64 * 128 * 2)>>>(A, B, Cf, Ch, M, N, K, epi);
}
static inline void mm64(const __half* A, const __half* B, float* Cf, __half* Ch,
                        int M, int K, int epi, int splits)
{
    dim3 grid(1, M / 128, splits);
    hgemm<64><<<grid, 256, STG * (A_STAGE + 64 * 64 * 2)>>>(A, B, Cf, Ch, M, 64, K, epi);
}

extern "C" void kernel_launch(void* const* d_in, const int* in_sizes, int n_in,
                              void* d_out, int out_size)
{
    const float* X       = (const float*)d_in[0];
    const int*   adjF    = (const int*)d_in[1];
    const int*   adjS    = (const int*)d_in[2];
    const float* W_enc1  = (const float*)d_in[3];
    const float* a_enc1  = (const float*)d_in[4];
    const float* W_enc2  = (const float*)d_in[5];
    const float* a_enc2  = (const float*)d_in[6];
    const float* W_dec1  = (const float*)d_in[7];
    const float* a_dec1  = (const float*)d_in[8];
    const float* W_dec2  = (const float*)d_in[9];
    const float* a_dec2  = (const float*)d_in[10];
    const float* w_omega = (const float*)d_in[11];
    const float* u_omega = (const float*)d_in[12];
    (void)in_sizes; (void)n_in; (void)out_size;

    cudaFuncSetAttribute(hgemm<128>, cudaFuncAttributeMaxDynamicSharedMemorySize,
                         STG * (A_STAGE + 64 * 128 * 2));
    cudaFuncSetAttribute(hgemm<64>, cudaFuncAttributeMaxDynamicSharedMemorySize,
                         STG * (A_STAGE + 64 * 64 * 2));

    float* out       = (float*)d_out;
    float* out_lat   = out;
    float* out_recon = out + (size_t)NN * DOUT;
    float* out_corr  = out_recon + (size_t)NN * DIN;
    float* out_alpha = out_corr + (size_t)NN * DOUT;

    __half *Xh, *W1h, *W2h, *Wd1h, *Wd2h, *att2, *wh1h, *h1h2, *whd1h, *wh2h2;
    __half *bigh, *reconh, *lath;
    uint32_t *adjPF, *adjPS;
    float *embF, *embS, *sbuf, *vu, *part;
    cudaGetSymbolAddress((void**)&Xh,    g_Xh);
    cudaGetSymbolAddress((void**)&W1h,   g_W1h);
    cudaGetSymbolAddress((void**)&W2h,   g_W2h);
    cudaGetSymbolAddress((void**)&Wd1h,  g_Wd1h);
    cudaGetSymbolAddress((void**)&Wd2h,  g_Wd2h);
    cudaGetSymbolAddress((void**)&att2,  g_att2h);
    cudaGetSymbolAddress((void**)&wh1h,  g_wh1h);
    cudaGetSymbolAddress((void**)&h1h2,  g_h1h2);
    cudaGetSymbolAddress((void**)&whd1h, g_whd1h);
    cudaGetSymbolAddress((void**)&wh2h2, g_wh2h2);
    cudaGetSymbolAddress((void**)&bigh,  g_bigh);
    cudaGetSymbolAddress((void**)&reconh,g_reconh);
    cudaGetSymbolAddress((void**)&lath,  g_lath);
    cudaGetSymbolAddress((void**)&adjPF, g_adjPF);
    cudaGetSymbolAddress((void**)&adjPS, g_adjPS);
    cudaGetSymbolAddress((void**)&embF,  g_embF);
    cudaGetSymbolAddress((void**)&embS,  g_embS);
    cudaGetSymbolAddress((void**)&sbuf,  g_s);
    cudaGetSymbolAddress((void**)&vu,    g_vu);
    cudaGetSymbolAddress((void**)&part,  g_part);

    float* sA1 = sbuf;              float* sB1 = sbuf + NN;
    float* sA2 = sbuf + 2 * NN;     float* sB2 = sbuf + 4 * NN;   // 2NN each

    // ===== one-time conversions =====
    f2h4<<<(NN * DIN / 4 + 255) / 256, 256>>>((const float4*)X, Xh, NN * DIN / 4);
    f2h4<<<(DIN * DHID / 4 + 255) / 256, 256>>>((const float4*)W_enc1, W1h, DIN * DHID / 4);
    f2h4<<<(DHID * DOUT / 4 + 255) / 256, 256>>>((const float4*)W_enc2, W2h, DHID * DOUT / 4);
    f2h4<<<(DOUT * DHID / 4 + 255) / 256, 256>>>((const float4*)W_dec1, Wd1h, DOUT * DHID / 4);
    f2h4<<<(DHID * DIN / 4 + 255) / 256, 256>>>((const float4*)W_dec2, Wd2h, DHID * DIN / 4);
    pack_adj<<<(NN * NN / 32 + 255) / 256, 256>>>(adjF, adjPF, NN * NN / 32);
    pack_adj<<<(NN * NN / 32 + 255) / 256, 256>>>(adjS, adjPS, NN * NN / 32);

    // batched encoder (both views), from half input 'src' -> embF/embS
    auto encode_both = [&](const __half* src, int Ksrc) {
        mm128(src, W1h, part, 0, NN, DHID, Ksrc, 0, 2);                   // WH1 (split 2)
        reduce_epi<<<(NN * DHID + 255) / 256, 256>>>(part, 0, wh1h, NN * DHID, 2, 0);
        scores_kernel<<<NN, 256>>>(wh1h, DHID, a_enc1, sA1, sB1);
        att_kernel<<<2 * NN, 256>>>(sA1, sB1, adjPF, adjPS, att2, 0);
        mm128(att2, wh1h, 0, h1h2, 2 * NN, DHID, NN, 1, 1);               // elu(att@WH1)
        mm64(h1h2, W2h, part, 0, 2 * NN, DHID, 0, 4);                     // WH2 (split 4)
        reduce_epi<<<(2 * NN * DOUT + 255) / 256, 256>>>(part, 0, wh2h2, 2 * NN * DOUT, 4, 0);
        scores_kernel<<<2 * NN, 256>>>(wh2h2, DOUT, a_enc2, sA2, sB2);
        att_kernel<<<2 * NN, 256>>>(sA2, sB2, adjPF, adjPS, att2, 1);
        mm64(att2, wh2h2, part, 0, NN, NN, 0, 8);                         // view F
        reduce_epi<<<(NN * DOUT + 255) / 256, 256>>>(part, embF, 0, NN * DOUT, 8, 1);
        mm64(att2 + (size_t)NN * NN, wh2h2 + (size_t)NN * DOUT, part, 0, NN, NN, 0, 8);
        reduce_epi<<<(NN * DOUT + 255) / 256, 256>>>(part, embS, 0, NN * DOUT, 8, 1);
    };

    // ===== encode(features, both views) =====
    encode_both(Xh, DIN);

    // ===== attention fusion -> emb_latent, alpha =====
    vu_kernel<<<NN, 64>>>(embF, w_omega, u_omega, vu);
    vu_kernel<<<NN, 64>>>(embS, w_omega, u_omega, vu + NN);
    fuse_kernel<<<NN, 64>>>(embF, embS, vu, vu + NN, out_lat, lath, out_alpha);

    // ===== decode (spatial adjacency) -> recon =====
    mm128(lath, Wd1h, 0, whd1h, NN, DHID, DOUT, 0, 1);                    // WHd1
    scores_kernel<<<NN, 256>>>(whd1h, DHID, a_dec1, sA2, sB2);
    att_kernel<<<NN, 256>>>(sA2, sB2, adjPS, adjPS, att2, 0);
    mm128(att2, whd1h, part, 0, NN, DHID, NN, 0, 2);                      // att@WHd1 (split 2)
    reduce_epi<<<(NN * DHID + 255) / 256, 256>>>(part, 0, h1h2, NN * DHID, 2, 1); // elu
    mm128(h1h2, Wd2h, 0, bigh, NN, DIN, DHID, 0, 1);                      // WHd2 [4096,3000]
    scores_kernel<<<NN, 256>>>(bigh, DIN, a_dec2, sA2, sB2);
    att_kernel<<<NN, 256>>>(sA2, sB2, adjPS, adjPS, att2, 0);
    mm128(att2, bigh, out_recon, reconh, NN, DIN, NN, 1, 1);              // recon

    // ===== corr = fuse(encode(recon, feat), encode(recon, spatial)) =====
    encode_both(reconh, DIN);
    vu_kernel<<<NN, 64>>>(embF, w_omega, u_omega, vu);
    vu_kernel<<<NN, 64>>>(embS, w_omega, u_omega, vu + NN);
    fuse_kernel<<<NN, 64>>>(embF, embS, vu, vu + NN, out_corr, (__half*)0, (float*)0);
}